// round 4
// baseline (speedup 1.0000x reference)
#include <cuda_runtime.h>

// SpikeLayer LIF timestep, elementwise over N = 16*56*56*256 = 12,845,056 fp32.
// Inputs: impulse, mem, mem_acc, refrac_until, spikecounts.
// Output: 6 stacked tensors [spikes, mem_out, mem_acc_out, refrac_out, counts_out, spiketrain].
//
// spikes ∈ {0,1}:
//   mem_out    = new_mem - spikes
//   counts_out = spikecounts + spikes
//   spiketrain = 0.5f * spikes
//   refrac_out = spikes ? 2.5f : refrac_until
//
// R3: back to VPT=1 (32 regs, occ ~76%), with streaming cache hints:
// __ldcs on the 5 zero-reuse input streams, __stcs on the 6 write-once output
// streams. Targets HBM R/W-turnaround efficiency (DRAM was pinned at ~80%
// of spec with both occ=76% and occ=41% variants -> request supply is not
// the limit; eviction/writeback behavior is the remaining lever).

#define TIME_C 0.5f
#define VTH_C 1.0f
#define REFRAC_SET 2.5f

__global__ void __launch_bounds__(256) spike_layer_kernel(
    const float4* __restrict__ impulse,
    const float4* __restrict__ mem,
    const float4* __restrict__ mem_acc,
    const float4* __restrict__ refrac_until,
    const float4* __restrict__ spikecounts,
    float4* __restrict__ out,   // 6 * nvec float4s
    int nvec)
{
    int i = blockIdx.x * blockDim.x + threadIdx.x;
    if (i >= nvec) return;

    float4 imp = __ldcs(&impulse[i]);
    float4 m   = __ldcs(&mem[i]);
    float4 ma  = __ldcs(&mem_acc[i]);
    float4 ru  = __ldcs(&refrac_until[i]);
    float4 sc  = __ldcs(&spikecounts[i]);

    float4 spikes, mem_out, ma_out, ru_out, sc_out, st_out;

    #pragma unroll
    for (int c = 0; c < 4; c++) {
        float impv = (&imp.x)[c];
        float mv   = (&m.x)[c];
        float mav  = (&ma.x)[c];
        float ruv  = (&ru.x)[c];
        float scv  = (&sc.x)[c];

        float masked = (ruv > TIME_C) ? 0.0f : impv;
        float new_mem = mv + masked;
        float spk = (new_mem >= VTH_C) ? 1.0f : 0.0f;

        (&spikes.x)[c]  = spk;
        (&mem_out.x)[c] = new_mem - spk;
        (&ma_out.x)[c]  = mav + masked;
        (&ru_out.x)[c]  = (spk != 0.0f) ? REFRAC_SET : ruv;
        (&sc_out.x)[c]  = scv + spk;
        (&st_out.x)[c]  = TIME_C * spk;
    }

    size_t nv = (size_t)nvec;
    __stcs(&out[0 * nv + i], spikes);
    __stcs(&out[1 * nv + i], mem_out);
    __stcs(&out[2 * nv + i], ma_out);
    __stcs(&out[3 * nv + i], ru_out);
    __stcs(&out[4 * nv + i], sc_out);
    __stcs(&out[5 * nv + i], st_out);
}

extern "C" void kernel_launch(void* const* d_in, const int* in_sizes, int n_in,
                              void* d_out, int out_size)
{
    const float* impulse      = (const float*)d_in[0];
    const float* mem          = (const float*)d_in[1];
    const float* mem_acc      = (const float*)d_in[2];
    const float* refrac_until = (const float*)d_in[3];
    const float* spikecounts  = (const float*)d_in[4];

    int n = in_sizes[0];          // 12,845,056 — divisible by 4
    int nvec = n / 4;             // 3,211,264

    int threads = 256;
    int blocks = (nvec + threads - 1) / threads;   // 12544

    spike_layer_kernel<<<blocks, threads>>>(
        (const float4*)impulse,
        (const float4*)mem,
        (const float4*)mem_acc,
        (const float4*)refrac_until,
        (const float4*)spikecounts,
        (float4*)d_out,
        nvec);
}